// round 7
// baseline (speedup 1.0000x reference)
#include <cuda_runtime.h>
#include <cstdint>

// ---------------------------------------------------------------------------
// LaneAttention: per-lane MLP score -> per-group(8) softmax -> weighted pool
// M = 262144 lanes, groups of 8 contiguous lanes, N = 32768, out [N,192]
//
// R7 = R5 (block-wide double-buffered cp.async staging + all weights in the
// constant bank) + 5 CTAs/SM + L2 prefetch of this block's fut rows so the
// phase-2 fut reads are L2 hits instead of exposed DRAM latency.
// ---------------------------------------------------------------------------

static constexpr int TPB = 256;        // threads = rows per block
static constexpr int CS  = 5;          // chunk-buffer row stride in float4 (4 data + 1 pad)
static constexpr int CHUNK_F4 = TPB * CS;            // 1280 float4 per buffer

__constant__ float cW1[128 * 16];      // 8 KB

__device__ __forceinline__ unsigned long long pack_dup(float x) {
    unsigned long long r;
    asm("mov.b64 %0, {%1, %1};" : "=l"(r) : "f"(x));
    return r;
}
__device__ __forceinline__ unsigned long long pack_xy(float x, float y) {
    unsigned long long r;
    asm("mov.b64 %0, {%1, %2};" : "=l"(r) : "f"(x), "f"(y));
    return r;
}
__device__ __forceinline__ void ffma2(unsigned long long &d, unsigned long long a, unsigned long long b) {
    asm("fma.rn.f32x2 %0, %1, %2, %0;" : "+l"(d) : "l"(a), "l"(b));
}
__device__ __forceinline__ float2 unpack2(unsigned long long v) {
    float2 f;
    asm("mov.b64 {%0, %1}, %2;" : "=f"(f.x), "=f"(f.y) : "l"(v));
    return f;
}
__device__ __forceinline__ void cp_async16(uint32_t dst_smem, const void* src) {
    asm volatile("cp.async.cg.shared.global [%0], [%1], 16;\n"
                 :: "r"(dst_smem), "l"(src) : "memory");
}
__device__ __forceinline__ void cp_commit() {
    asm volatile("cp.async.commit_group;\n");
}
template <int N>
__device__ __forceinline__ void cp_wait() {
    asm volatile("cp.async.wait_group %0;\n" :: "n"(N) : "memory");
}

extern __shared__ float smem_f[];
// layout (floats): xbuf 2*1280*4 = 10240 | probs 256 | outrow 32 ints
static constexpr int PROBS_OFF  = 2 * CHUNK_F4 * 4;                 // 10240
static constexpr int SMEM_BYTES = (PROBS_OFF + 256) * 4 + 128;      // ~42.1 KB

// stage 16 columns (4 float4) of all 256 rows of `arr` chunk cc&3 into buffer b
__device__ __forceinline__ void stage_chunk(const float* arr, int row0, int cc,
                                            int b, int tid, uint32_t smem_base)
{
    const float4* src = (const float4*)(arr + (size_t)row0 * 64) + (cc & 3) * 4;
    #pragma unroll
    for (int u = 0; u < 4; ++u) {
        int f = tid + 256 * u;          // flat float4 idx 0..1023
        int r = f >> 2, c = f & 3;
        cp_async16(smem_base + (uint32_t)(b * CHUNK_F4 + r * CS + c) * 16u,
                   src + r * 16 + c);
    }
    cp_commit();
}

__global__ __launch_bounds__(TPB, 5)
void lane_attn_kernel(const float* __restrict__ ht,
                      const float* __restrict__ info,
                      const float* __restrict__ fut,
                      const float* __restrict__ b1,   // [16]
                      const float* __restrict__ W2,   // [16]
                      const float* __restrict__ b2,   // [1]
                      const int*   __restrict__ seg,  // [M]
                      float* __restrict__ out)        // [N,192]
{
    float*  probs  = smem_f + PROBS_OFF;
    int*    outrow = (int*)(probs + TPB);
    const float4* xbuf4 = (const float4*)smem_f;

    const int tid  = threadIdx.x;
    const int row0 = blockIdx.x * TPB;
    const uint32_t xb_s = (uint32_t)__cvta_generic_to_shared(smem_f);

    // kick off the staging pipeline immediately
    stage_chunk(ht, row0, 0, 0, tid, xb_s);
    stage_chunk(ht, row0, 1, 1, tid, xb_s);

    // L2-prefetch this block's fut rows (64 KB = 512 lines; 2 lines/thread)
    {
        const char* fp = (const char*)(fut + (size_t)row0 * 64);
        asm volatile("prefetch.global.L2 [%0];" :: "l"(fp + (size_t)tid * 128));
        asm volatile("prefetch.global.L2 [%0];" :: "l"(fp + (size_t)(tid + 256) * 128));
    }

    if (tid < 32)
        outrow[tid] = seg[row0 + tid * 8];

    unsigned long long hp[8];
    {
        const float2* b12 = (const float2*)b1;
        #pragma unroll
        for (int j = 0; j < 8; ++j) {
            float2 bv = b12[j];
            hp[j] = pack_xy(bv.x, bv.y);
        }
    }

    // ---- phase 1: 8 chunks (4 ht + 4 info), double-buffered ------------------
    #pragma unroll
    for (int cc = 0; cc < 8; ++cc) {
        if (cc < 7) cp_wait<1>(); else cp_wait<0>();
        __syncthreads();                      // staged data visible to all

        const int b = cc & 1;
        const float4* xb = xbuf4 + b * CHUNK_F4 + tid * CS;
        #pragma unroll
        for (int q2 = 0; q2 < 4; ++q2) {
            float4 v = xb[q2];
            float xs[4] = {v.x, v.y, v.z, v.w};
            #pragma unroll
            for (int c = 0; c < 4; ++c) {
                const int k = cc * 16 + q2 * 4 + c;   // weight row, compile-time
                unsigned long long xv = pack_dup(xs[c]);
                // constant-port loads: immediate address, warp-uniform
                const double2* wr = (const double2*)(cW1 + k * 16);
                double2 w01 = wr[0];
                double2 w23 = wr[1];
                ffma2(hp[0], xv, __double_as_longlong(w01.x));
                ffma2(hp[1], xv, __double_as_longlong(w01.y));
                ffma2(hp[2], xv, __double_as_longlong(w23.x));
                ffma2(hp[3], xv, __double_as_longlong(w23.y));
                double2 w45 = wr[2];
                double2 w67 = wr[3];
                ffma2(hp[4], xv, __double_as_longlong(w45.x));
                ffma2(hp[5], xv, __double_as_longlong(w45.y));
                ffma2(hp[6], xv, __double_as_longlong(w67.x));
                ffma2(hp[7], xv, __double_as_longlong(w67.y));
            }
        }
        __syncthreads();                      // all reads of buffer b done
        if (cc + 2 < 8)                        // refill the buffer just consumed
            stage_chunk(cc + 2 < 4 ? ht : info, row0, cc + 2, b, tid, xb_s);
    }

    // ReLU + second layer -> score
    float score = b2[0];
    #pragma unroll
    for (int j = 0; j < 8; ++j) {
        float2 h2 = unpack2(hp[j]);
        score += fmaxf(h2.x, 0.f) * W2[2 * j]
               + fmaxf(h2.y, 0.f) * W2[2 * j + 1];
    }

    // ---- group-of-8 softmax (warp-aligned groups) -----------------------------
    float m = score;
    #pragma unroll
    for (int d = 1; d < 8; d <<= 1)
        m = fmaxf(m, __shfl_xor_sync(0xffffffffu, m, d));
    float e = __expf(score - m);
    float s = e;
    #pragma unroll
    for (int d = 1; d < 8; d <<= 1)
        s += __shfl_xor_sync(0xffffffffu, s, d);
    probs[tid] = e / s;

    __syncthreads();

    // ---- phase 2: weighted pooling, float4 per lane (all reads L2-warm) ------
    const int wrp = tid >> 5;
    const int h   = (tid >> 4) & 1;
    const int k   = tid & 15;

    #pragma unroll
    for (int it = 0; it < 2; ++it) {
        const int gloc  = wrp * 4 + it * 2 + h;          // local group 0..31
        const int lbase = gloc * 8;
        const float4* hb = (const float4*)(ht   + (size_t)(row0 + lbase) * 64);
        const float4* ib = (const float4*)(info + (size_t)(row0 + lbase) * 64);
        const float4* fb = (const float4*)(fut  + (size_t)(row0 + lbase) * 64);

        float4 ah = make_float4(0.f, 0.f, 0.f, 0.f);
        float4 ai = ah, af = ah;
        #pragma unroll
        for (int j = 0; j < 8; ++j) {
            const float p = probs[lbase + j];
            float4 hv = hb[j * 16 + k];                   // L2 hit (phase-1 resident)
            float4 iv = ib[j * 16 + k];                   // L2 hit
            float4 fv = fb[j * 16 + k];                   // L2 hit (prefetched)
            ah.x += p * hv.x; ah.y += p * hv.y; ah.z += p * hv.z; ah.w += p * hv.w;
            ai.x += p * iv.x; ai.y += p * iv.y; ai.z += p * iv.z; ai.w += p * iv.w;
            af.x += p * fv.x; af.y += p * fv.y; af.z += p * fv.z; af.w += p * fv.w;
        }
        float4* o4 = (float4*)(out + (size_t)outrow[gloc] * 192);
        o4[k]      = ah;
        o4[16 + k] = ai;
        o4[32 + k] = af;
    }
}

extern "C" void kernel_launch(void* const* d_in, const int* in_sizes, int n_in,
                              void* d_out, int out_size)
{
    const float* ht   = (const float*)d_in[0];
    const float* info = (const float*)d_in[1];
    const float* fut  = (const float*)d_in[2];
    const float* W1   = (const float*)d_in[3];
    const float* b1   = (const float*)d_in[4];
    const float* W2   = (const float*)d_in[5];
    const float* b2   = (const float*)d_in[6];
    const int*   seg  = (const int*)d_in[7];
    float* out = (float*)d_out;

    const int M = in_sizes[0] / 64;          // 262144
    const int nblocks = M / TPB;             // 1024

    static void* cw1_addr = nullptr;
    if (!cw1_addr) {
        cudaGetSymbolAddress(&cw1_addr, cW1);
        cudaFuncSetAttribute(lane_attn_kernel,
                             cudaFuncAttributeMaxDynamicSharedMemorySize, SMEM_BYTES);
    }

    // D2D async copy into the constant bank — one graph memcpy node
    cudaMemcpyAsync(cw1_addr, W1, 128 * 16 * sizeof(float), cudaMemcpyDeviceToDevice);

    lane_attn_kernel<<<nblocks, TPB, SMEM_BYTES>>>(ht, info, fut, b1, W2, b2, seg, out);
}

// round 8
// speedup vs baseline: 1.1091x; 1.1091x over previous
#include <cuda_runtime.h>
#include <cstdint>

// ---------------------------------------------------------------------------
// LaneAttention: per-lane MLP score -> per-group(8) softmax -> weighted pool
// M = 262144 lanes, groups of 8 contiguous lanes, N = 32768, out [N,192]
//
// R8 = R5 core (block-wide cp.async staging, weights in constant bank,
// phase-2 pooling from L2, 4 CTAs/SM) with:
//   * weight reads split across ports: even W1 rows -> constant (LDC),
//     odd rows -> smem (LDS.128 broadcast)
//   * deeper staging pipeline: 16 half-chunks x 4 buffers (depth-3 prefetch)
// ---------------------------------------------------------------------------

static constexpr int TPB   = 256;      // threads = rows per block
static constexpr int RS    = 3;        // buffer row stride in float4 (2 data + 1 pad)
static constexpr int BUF_F4 = TPB * RS;          // 768 float4 per buffer
static constexpr int NBUF  = 4;

__constant__ float cW1[128 * 16];      // 8 KB

__device__ __forceinline__ unsigned long long pack_dup(float x) {
    unsigned long long r;
    asm("mov.b64 %0, {%1, %1};" : "=l"(r) : "f"(x));
    return r;
}
__device__ __forceinline__ unsigned long long pack_xy(float x, float y) {
    unsigned long long r;
    asm("mov.b64 %0, {%1, %2};" : "=l"(r) : "f"(x), "f"(y));
    return r;
}
__device__ __forceinline__ void ffma2(unsigned long long &d, unsigned long long a, unsigned long long b) {
    asm("fma.rn.f32x2 %0, %1, %2, %0;" : "+l"(d) : "l"(a), "l"(b));
}
__device__ __forceinline__ float2 unpack2(unsigned long long v) {
    float2 f;
    asm("mov.b64 {%0, %1}, %2;" : "=f"(f.x), "=f"(f.y) : "l"(v));
    return f;
}
__device__ __forceinline__ void cp_async16(uint32_t dst_smem, const void* src) {
    asm volatile("cp.async.cg.shared.global [%0], [%1], 16;\n"
                 :: "r"(dst_smem), "l"(src) : "memory");
}
__device__ __forceinline__ void cp_commit() {
    asm volatile("cp.async.commit_group;\n");
}
template <int N>
__device__ __forceinline__ void cp_wait() {
    asm volatile("cp.async.wait_group %0;\n" :: "n"(N) : "memory");
}

extern __shared__ float smem_f[];
// layout (floats):
//   xbuf : 4 bufs * 768 f4 = 3072 f4 = 12288 floats (48 KB)
//   w1s  : odd W1 rows, 64*16 = 1024 floats (4 KB)
//   probs: 256
//   outrow: 32 ints
static constexpr int W1S_OFF   = NBUF * BUF_F4 * 4;                 // 12288
static constexpr int PROBS_OFF = W1S_OFF + 1024;
static constexpr int SMEM_BYTES = (PROBS_OFF + 256) * 4 + 128;      // ~54.4 KB

// stage 8 columns (2 float4) of all 256 rows of chunk cc into buffer b
__device__ __forceinline__ void stage_chunk(const float* arr, int row0, int cc,
                                            int b, int tid, uint32_t smem_base)
{
    const float4* src = (const float4*)(arr + (size_t)row0 * 64) + (cc & 7) * 2;
    #pragma unroll
    for (int u = 0; u < 2; ++u) {
        int f = tid + 256 * u;          // flat float4 idx 0..511
        int r = f >> 1, c = f & 1;
        cp_async16(smem_base + (uint32_t)(b * BUF_F4 + r * RS + c) * 16u,
                   src + r * 16 + c);
    }
    cp_commit();
}

__global__ __launch_bounds__(TPB, 4)
void lane_attn_kernel(const float* __restrict__ ht,
                      const float* __restrict__ info,
                      const float* __restrict__ fut,
                      const float* __restrict__ b1,   // [16]
                      const float* __restrict__ W2,   // [16]
                      const float* __restrict__ b2,   // [1]
                      const int*   __restrict__ seg,  // [M]
                      float* __restrict__ out)        // [N,192]
{
    float*  w1s    = smem_f + W1S_OFF;
    float*  probs  = smem_f + PROBS_OFF;
    int*    outrow = (int*)(probs + TPB);
    const float4* xbuf4 = (const float4*)smem_f;

    const int tid  = threadIdx.x;
    const int row0 = blockIdx.x * TPB;
    const uint32_t xb_s = (uint32_t)__cvta_generic_to_shared(smem_f);

    // prime the pipeline: chunks 0..3 in flight
    stage_chunk(ht, row0, 0, 0, tid, xb_s);
    stage_chunk(ht, row0, 1, 1, tid, xb_s);
    stage_chunk(ht, row0, 2, 2, tid, xb_s);
    stage_chunk(ht, row0, 3, 3, tid, xb_s);

    // stage odd W1 rows into smem: w1s[m*16+j] = cW1[(2m+1)*16+j]
    #pragma unroll
    for (int i = 0; i < 4; ++i) {
        int idx = tid * 4 + i;          // 0..1023
        w1s[idx] = cW1[(idx >> 4) * 32 + 16 + (idx & 15)];
    }
    if (tid < 32)
        outrow[tid] = seg[row0 + tid * 8];

    unsigned long long hp[8];
    {
        const float2* b12 = (const float2*)b1;
        #pragma unroll
        for (int j = 0; j < 8; ++j) {
            float2 bv = b12[j];
            hp[j] = pack_xy(bv.x, bv.y);
        }
    }

    // ---- phase 1: 16 chunks (8 ht + 8 info), 4-buffer pipeline ---------------
    #pragma unroll
    for (int cc = 0; cc < 16; ++cc) {
        if      (cc <= 12) cp_wait<3>();
        else if (cc == 13) cp_wait<2>();
        else if (cc == 14) cp_wait<1>();
        else               cp_wait<0>();
        __syncthreads();                       // staged data visible to all

        const int b = cc & 3;
        const float4* xb = xbuf4 + b * BUF_F4 + tid * RS;
        float4 v0 = xb[0];
        float4 v1 = xb[1];
        float xs[8] = {v0.x, v0.y, v0.z, v0.w, v1.x, v1.y, v1.z, v1.w};
        #pragma unroll
        for (int c = 0; c < 8; ++c) {
            const int k = cc * 8 + c;          // weight row, compile-time
            unsigned long long xv = pack_dup(xs[c]);
            // port split: even rows -> constant bank, odd rows -> smem
            const double2* wr = (k & 1)
                ? (const double2*)(w1s + (k >> 1) * 16)
                : (const double2*)(cW1 + k * 16);
            double2 w01 = wr[0];
            double2 w23 = wr[1];
            ffma2(hp[0], xv, __double_as_longlong(w01.x));
            ffma2(hp[1], xv, __double_as_longlong(w01.y));
            ffma2(hp[2], xv, __double_as_longlong(w23.x));
            ffma2(hp[3], xv, __double_as_longlong(w23.y));
            double2 w45 = wr[2];
            double2 w67 = wr[3];
            ffma2(hp[4], xv, __double_as_longlong(w45.x));
            ffma2(hp[5], xv, __double_as_longlong(w45.y));
            ffma2(hp[6], xv, __double_as_longlong(w67.x));
            ffma2(hp[7], xv, __double_as_longlong(w67.y));
        }
        __syncthreads();                       // all reads of buffer b done
        if (cc + 4 < 16)                       // refill the buffer just consumed
            stage_chunk(cc + 4 < 8 ? ht : info, row0, cc + 4, b, tid, xb_s);
    }

    // ReLU + second layer -> score
    float score = b2[0];
    #pragma unroll
    for (int j = 0; j < 8; ++j) {
        float2 h2 = unpack2(hp[j]);
        score += fmaxf(h2.x, 0.f) * W2[2 * j]
               + fmaxf(h2.y, 0.f) * W2[2 * j + 1];
    }

    // ---- group-of-8 softmax (warp-aligned groups) -----------------------------
    float m = score;
    #pragma unroll
    for (int d = 1; d < 8; d <<= 1)
        m = fmaxf(m, __shfl_xor_sync(0xffffffffu, m, d));
    float e = __expf(score - m);
    float s = e;
    #pragma unroll
    for (int d = 1; d < 8; d <<= 1)
        s += __shfl_xor_sync(0xffffffffu, s, d);
    probs[tid] = e / s;

    __syncthreads();

    // ---- phase 2: weighted pooling, float4 per lane (ht/info from L2) --------
    const int wrp = tid >> 5;
    const int h   = (tid >> 4) & 1;
    const int k   = tid & 15;

    #pragma unroll
    for (int it = 0; it < 2; ++it) {
        const int gloc  = wrp * 4 + it * 2 + h;          // local group 0..31
        const int lbase = gloc * 8;
        const float4* hb = (const float4*)(ht   + (size_t)(row0 + lbase) * 64);
        const float4* ib = (const float4*)(info + (size_t)(row0 + lbase) * 64);
        const float4* fb = (const float4*)(fut  + (size_t)(row0 + lbase) * 64);

        float4 ah = make_float4(0.f, 0.f, 0.f, 0.f);
        float4 ai = ah, af = ah;
        #pragma unroll
        for (int j = 0; j < 8; ++j) {
            const float p = probs[lbase + j];
            float4 hv = hb[j * 16 + k];                   // L2 hit (phase-1 resident)
            float4 iv = ib[j * 16 + k];                   // L2 hit
            float4 fv = __ldcs(fb + j * 16 + k);          // single-use stream
            ah.x += p * hv.x; ah.y += p * hv.y; ah.z += p * hv.z; ah.w += p * hv.w;
            ai.x += p * iv.x; ai.y += p * iv.y; ai.z += p * iv.z; ai.w += p * iv.w;
            af.x += p * fv.x; af.y += p * fv.y; af.z += p * fv.z; af.w += p * fv.w;
        }
        float4* o4 = (float4*)(out + (size_t)outrow[gloc] * 192);
        o4[k]      = ah;
        o4[16 + k] = ai;
        o4[32 + k] = af;
    }
}

extern "C" void kernel_launch(void* const* d_in, const int* in_sizes, int n_in,
                              void* d_out, int out_size)
{
    const float* ht   = (const float*)d_in[0];
    const float* info = (const float*)d_in[1];
    const float* fut  = (const float*)d_in[2];
    const float* W1   = (const float*)d_in[3];
    const float* b1   = (const float*)d_in[4];
    const float* W2   = (const float*)d_in[5];
    const float* b2   = (const float*)d_in[6];
    const int*   seg  = (const int*)d_in[7];
    float* out = (float*)d_out;

    const int M = in_sizes[0] / 64;          // 262144
    const int nblocks = M / TPB;             // 1024

    static void* cw1_addr = nullptr;
    if (!cw1_addr) {
        cudaGetSymbolAddress(&cw1_addr, cW1);
        cudaFuncSetAttribute(lane_attn_kernel,
                             cudaFuncAttributeMaxDynamicSharedMemorySize, SMEM_BYTES);
    }

    // D2D async copy into the constant bank — one graph memcpy node
    cudaMemcpyAsync(cw1_addr, W1, 128 * 16 * sizeof(float), cudaMemcpyDeviceToDevice);

    lane_attn_kernel<<<nblocks, TPB, SMEM_BYTES>>>(ht, info, fut, b1, W2, b2, seg, out);
}

// round 9
// speedup vs baseline: 1.5421x; 1.3904x over previous
#include <cuda_runtime.h>
#include <cstdint>

// ---------------------------------------------------------------------------
// LaneAttention: per-lane MLP score -> per-group(8) softmax -> weighted pool
// M = 262144 lanes, groups of 8 contiguous lanes, N = 32768, out [N,192]
//
// R9 = R5 core unchanged (block-wide double-buffered cp.async staging, all
// weights in the constant bank, phase-2 pooling from L2, __ldcs fut), but
// re-tiled to TPB=128 / grid=2048 / 7 CTAs/SM so the launch is 1.98 balanced
// waves (vs R5's 1.73 waves with 160 SM-slots idle in wave 2).
// ---------------------------------------------------------------------------

static constexpr int TPB = 128;        // threads = rows per block
static constexpr int CS  = 5;          // chunk-buffer row stride in float4 (4 data + 1 pad)
static constexpr int CHUNK_F4 = TPB * CS;            // 640 float4 per buffer

__constant__ float cW1[128 * 16];      // 8 KB

__device__ __forceinline__ unsigned long long pack_dup(float x) {
    unsigned long long r;
    asm("mov.b64 %0, {%1, %1};" : "=l"(r) : "f"(x));
    return r;
}
__device__ __forceinline__ unsigned long long pack_xy(float x, float y) {
    unsigned long long r;
    asm("mov.b64 %0, {%1, %2};" : "=l"(r) : "f"(x), "f"(y));
    return r;
}
__device__ __forceinline__ void ffma2(unsigned long long &d, unsigned long long a, unsigned long long b) {
    asm("fma.rn.f32x2 %0, %1, %2, %0;" : "+l"(d) : "l"(a), "l"(b));
}
__device__ __forceinline__ float2 unpack2(unsigned long long v) {
    float2 f;
    asm("mov.b64 {%0, %1}, %2;" : "=f"(f.x), "=f"(f.y) : "l"(v));
    return f;
}
__device__ __forceinline__ void cp_async16(uint32_t dst_smem, const void* src) {
    asm volatile("cp.async.cg.shared.global [%0], [%1], 16;\n"
                 :: "r"(dst_smem), "l"(src) : "memory");
}
__device__ __forceinline__ void cp_commit() {
    asm volatile("cp.async.commit_group;\n");
}
template <int N>
__device__ __forceinline__ void cp_wait() {
    asm volatile("cp.async.wait_group %0;\n" :: "n"(N) : "memory");
}

extern __shared__ float smem_f[];
// layout (floats): xbuf 2*640*4 = 5120 | probs 128 | outrow 16 ints
static constexpr int PROBS_OFF  = 2 * CHUNK_F4 * 4;                 // 5120
static constexpr int SMEM_BYTES = (PROBS_OFF + TPB) * 4 + 128;      // ~21.1 KB

// stage 16 columns (4 float4) of all 128 rows of `arr` chunk cc&3 into buffer b
__device__ __forceinline__ void stage_chunk(const float* arr, int row0, int cc,
                                            int b, int tid, uint32_t smem_base)
{
    const float4* src = (const float4*)(arr + (size_t)row0 * 64) + (cc & 3) * 4;
    #pragma unroll
    for (int u = 0; u < 4; ++u) {
        int f = tid + TPB * u;          // flat float4 idx 0..511
        int r = f >> 2, c = f & 3;
        cp_async16(smem_base + (uint32_t)(b * CHUNK_F4 + r * CS + c) * 16u,
                   src + r * 16 + c);
    }
    cp_commit();
}

__global__ __launch_bounds__(TPB, 7)
void lane_attn_kernel(const float* __restrict__ ht,
                      const float* __restrict__ info,
                      const float* __restrict__ fut,
                      const float* __restrict__ b1,   // [16]
                      const float* __restrict__ W2,   // [16]
                      const float* __restrict__ b2,   // [1]
                      const int*   __restrict__ seg,  // [M]
                      float* __restrict__ out)        // [N,192]
{
    float*  probs  = smem_f + PROBS_OFF;
    int*    outrow = (int*)(probs + TPB);
    const float4* xbuf4 = (const float4*)smem_f;

    const int tid  = threadIdx.x;
    const int row0 = blockIdx.x * TPB;
    const uint32_t xb_s = (uint32_t)__cvta_generic_to_shared(smem_f);

    // kick off the staging pipeline immediately
    stage_chunk(ht, row0, 0, 0, tid, xb_s);
    stage_chunk(ht, row0, 1, 1, tid, xb_s);

    if (tid < 16)
        outrow[tid] = seg[row0 + tid * 8];

    unsigned long long hp[8];
    {
        const float2* b12 = (const float2*)b1;
        #pragma unroll
        for (int j = 0; j < 8; ++j) {
            float2 bv = b12[j];
            hp[j] = pack_xy(bv.x, bv.y);
        }
    }

    // ---- phase 1: 8 chunks (4 ht + 4 info), double-buffered ------------------
    #pragma unroll
    for (int cc = 0; cc < 8; ++cc) {
        if (cc < 7) cp_wait<1>(); else cp_wait<0>();
        __syncthreads();                      // staged data visible to all

        const int b = cc & 1;
        const float4* xb = xbuf4 + b * CHUNK_F4 + tid * CS;
        #pragma unroll
        for (int q2 = 0; q2 < 4; ++q2) {
            float4 v = xb[q2];
            float xs[4] = {v.x, v.y, v.z, v.w};
            #pragma unroll
            for (int c = 0; c < 4; ++c) {
                const int k = cc * 16 + q2 * 4 + c;   // weight row, compile-time
                unsigned long long xv = pack_dup(xs[c]);
                // constant-port loads: immediate address, warp-uniform
                const double2* wr = (const double2*)(cW1 + k * 16);
                double2 w01 = wr[0];
                double2 w23 = wr[1];
                ffma2(hp[0], xv, __double_as_longlong(w01.x));
                ffma2(hp[1], xv, __double_as_longlong(w01.y));
                ffma2(hp[2], xv, __double_as_longlong(w23.x));
                ffma2(hp[3], xv, __double_as_longlong(w23.y));
                double2 w45 = wr[2];
                double2 w67 = wr[3];
                ffma2(hp[4], xv, __double_as_longlong(w45.x));
                ffma2(hp[5], xv, __double_as_longlong(w45.y));
                ffma2(hp[6], xv, __double_as_longlong(w67.x));
                ffma2(hp[7], xv, __double_as_longlong(w67.y));
            }
        }
        __syncthreads();                      // all reads of buffer b done
        if (cc + 2 < 8)                        // refill the buffer just consumed
            stage_chunk(cc + 2 < 4 ? ht : info, row0, cc + 2, b, tid, xb_s);
    }

    // ReLU + second layer -> score
    float score = b2[0];
    #pragma unroll
    for (int j = 0; j < 8; ++j) {
        float2 h2 = unpack2(hp[j]);
        score += fmaxf(h2.x, 0.f) * W2[2 * j]
               + fmaxf(h2.y, 0.f) * W2[2 * j + 1];
    }

    // ---- group-of-8 softmax (warp-aligned groups) -----------------------------
    float m = score;
    #pragma unroll
    for (int d = 1; d < 8; d <<= 1)
        m = fmaxf(m, __shfl_xor_sync(0xffffffffu, m, d));
    float e = __expf(score - m);
    float s = e;
    #pragma unroll
    for (int d = 1; d < 8; d <<= 1)
        s += __shfl_xor_sync(0xffffffffu, s, d);
    probs[tid] = e / s;

    __syncthreads();

    // ---- phase 2: weighted pooling, float4 per lane (ht/info from L2) --------
    const int wrp = tid >> 5;                // 0..3
    const int h   = (tid >> 4) & 1;
    const int k   = tid & 15;

    #pragma unroll
    for (int it = 0; it < 2; ++it) {
        const int gloc  = wrp * 4 + it * 2 + h;          // local group 0..15
        const int lbase = gloc * 8;
        const float4* hb = (const float4*)(ht   + (size_t)(row0 + lbase) * 64);
        const float4* ib = (const float4*)(info + (size_t)(row0 + lbase) * 64);
        const float4* fb = (const float4*)(fut  + (size_t)(row0 + lbase) * 64);

        float4 ah = make_float4(0.f, 0.f, 0.f, 0.f);
        float4 ai = ah, af = ah;
        #pragma unroll
        for (int j = 0; j < 8; ++j) {
            const float p = probs[lbase + j];
            float4 hv = hb[j * 16 + k];                   // L2 hit (phase-1 resident)
            float4 iv = ib[j * 16 + k];                   // L2 hit
            float4 fv = __ldcs(fb + j * 16 + k);          // single-use stream
            ah.x += p * hv.x; ah.y += p * hv.y; ah.z += p * hv.z; ah.w += p * hv.w;
            ai.x += p * iv.x; ai.y += p * iv.y; ai.z += p * iv.z; ai.w += p * iv.w;
            af.x += p * fv.x; af.y += p * fv.y; af.z += p * fv.z; af.w += p * fv.w;
        }
        float4* o4 = (float4*)(out + (size_t)outrow[gloc] * 192);
        o4[k]      = ah;
        o4[16 + k] = ai;
        o4[32 + k] = af;
    }
}

extern "C" void kernel_launch(void* const* d_in, const int* in_sizes, int n_in,
                              void* d_out, int out_size)
{
    const float* ht   = (const float*)d_in[0];
    const float* info = (const float*)d_in[1];
    const float* fut  = (const float*)d_in[2];
    const float* W1   = (const float*)d_in[3];
    const float* b1   = (const float*)d_in[4];
    const float* W2   = (const float*)d_in[5];
    const float* b2   = (const float*)d_in[6];
    const int*   seg  = (const int*)d_in[7];
    float* out = (float*)d_out;

    const int M = in_sizes[0] / 64;          // 262144
    const int nblocks = M / TPB;             // 2048

    static void* cw1_addr = nullptr;
    if (!cw1_addr) {
        cudaGetSymbolAddress(&cw1_addr, cW1);
        cudaFuncSetAttribute(lane_attn_kernel,
                             cudaFuncAttributeMaxDynamicSharedMemorySize, SMEM_BYTES);
    }

    // D2D async copy into the constant bank — one graph memcpy node
    cudaMemcpyAsync(cw1_addr, W1, 128 * 16 * sizeof(float), cudaMemcpyDeviceToDevice);

    lane_attn_kernel<<<nblocks, TPB, SMEM_BYTES>>>(ht, info, fut, b1, W2, b2, seg, out);
}